// round 2
// baseline (speedup 1.0000x reference)
#include <cuda_runtime.h>

typedef unsigned long long u64;

#define B_TOT 65536
#define D_DIM 256
#define U_DIM 256
#define T_TASK 2
#define EP 2
#define ES 2
#define NG 4      /* Ep+Es   */
#define NGS 6     /* T*Ep+Es */
#define BB 64
#define UU 64
#define KC 64

// Inter-level scratch: 3 x [B, U] fp32 (task0, task1, shared) = 192 MB static.
__device__ float g_mid[3ull * B_TOT * U_DIM];

struct Smem {
    u64   xdup[D_DIM][BB];          // input tile, transposed, each value duplicated as f32x2 (128 KB)
    float wts[KC][UU];              // weight k-chunk; also reused to stage gate weights (16 KB)
    float gate_t[T_TASK][BB][NG];   // per-task softmax gates
    float gate_s[BB][8];            // shared-path gates (6 used)
};

__device__ __forceinline__ u64 dupf(float v) {
    unsigned u = __float_as_uint(v);
    return ((u64)u << 32) | (u64)u;
}
__device__ __forceinline__ float lo32(u64 v) { return __uint_as_float((unsigned)(v & 0xffffffffull)); }
__device__ __forceinline__ float hi32(u64 v) { return __uint_as_float((unsigned)(v >> 32)); }
__device__ __forceinline__ void ffma2(u64& d, u64 a, u64 b) {
    asm("fma.rn.f32x2 %0, %1, %2, %0;" : "+l"(d) : "l"(a), "l"(b));
}

__global__ void __launch_bounds__(256, 1) ple_level_kernel(
    const float* __restrict__ in0, const float* __restrict__ in1, const float* __restrict__ insh,
    const float* __restrict__ we_task, const float* __restrict__ be_task,
    const float* __restrict__ we_share, const float* __restrict__ be_share,
    const float* __restrict__ wg_task, const float* __restrict__ bg_task,
    const float* __restrict__ wg_share, const float* __restrict__ bg_share,
    float* __restrict__ out0, float* __restrict__ out1, float* __restrict__ outs,
    int last)
{
    extern __shared__ char smem_raw[];
    Smem& sm = *reinterpret_cast<Smem*>(smem_raw);

    const int tid = threadIdx.x;
    const int tx = tid & 15;   // u direction (4 cols per thread)
    const int ty = tid >> 4;   // b direction (4 rows per thread)
    const int b0 = blockIdx.y * BB;
    const int u0 = blockIdx.x * UU;

    float outA[4][4], outB[4][4], outC[4][4];
    #pragma unroll
    for (int r = 0; r < 4; ++r)
        #pragma unroll
        for (int c = 0; c < 4; ++c) { outA[r][c] = 0.f; outB[r][c] = 0.f; outC[r][c] = 0.f; }

    const float* loaded = nullptr;

    // Load the [BB x D] input tile transposed + f32x2-duplicated into sm.xdup.
    auto load_tile = [&](const float* xin) {
        if (xin == loaded) return;
        __syncthreads();   // prior readers of xdup done
        const int row = tid & 63;
        const int cbase = (tid >> 6) * 16;
        const float4* src = reinterpret_cast<const float4*>(xin + (size_t)(b0 + row) * D_DIM);
        #pragma unroll 4
        for (int it = 0; it < 16; ++it) {
            int c4 = cbase + it;
            float4 v = src[c4];
            // lanes have consecutive rows -> contiguous 256B smem stores, conflict-free
            sm.xdup[4 * c4 + 0][row] = dupf(v.x);
            sm.xdup[4 * c4 + 1][row] = dupf(v.y);
            sm.xdup[4 * c4 + 2][row] = dupf(v.z);
            sm.xdup[4 * c4 + 3][row] = dupf(v.w);
        }
        loaded = xin;
        __syncthreads();   // xdup visible
    };

    // ================= PHASE 1: all gates (before any expert epilogue) =================
    const int n_gate_grps = last ? 2 : 3;
    #pragma unroll 1
    for (int gg = 0; gg < n_gate_grps; ++gg) {
        const float* xin = (gg == 0) ? in0 : (gg == 1) ? in1 : insh;
        load_tile(xin);

        __syncthreads();   // previous wts readers done
        float* wg_s = &sm.wts[0][0];
        if (gg < 2) {
            for (int i = tid; i < D_DIM * NG; i += 256) wg_s[i] = wg_task[gg * D_DIM * NG + i];
        } else {
            for (int i = tid; i < D_DIM * NGS; i += 256) wg_s[i] = wg_share[i];
        }
        __syncthreads();

        if (gg < 2) {
            const int r = tid >> 2, g = tid & 3;
            float acc = bg_task[gg * NG + g];
            #pragma unroll 8
            for (int d = 0; d < D_DIM; ++d)
                acc = fmaf(((const float*)&sm.xdup[d][r])[0], wg_s[d * NG + g], acc);
            float m = acc;
            m = fmaxf(m, __shfl_xor_sync(0xffffffffu, m, 1));
            m = fmaxf(m, __shfl_xor_sync(0xffffffffu, m, 2));
            float e = expf(acc - m);
            float s = e;
            s += __shfl_xor_sync(0xffffffffu, s, 1);
            s += __shfl_xor_sync(0xffffffffu, s, 2);
            sm.gate_t[gg][r][g] = e / s;
        } else {
            const int r0 = tid >> 3, g = tid & 7;
            #pragma unroll 1
            for (int h = 0; h < 2; ++h) {
                int r = r0 + 32 * h;
                float acc = -1e30f;
                if (g < NGS) {
                    acc = bg_share[g];
                    #pragma unroll 8
                    for (int d = 0; d < D_DIM; ++d)
                        acc = fmaf(((const float*)&sm.xdup[d][r])[0], wg_s[d * NGS + g], acc);
                }
                float m = acc;
                m = fmaxf(m, __shfl_xor_sync(0xffffffffu, m, 1));
                m = fmaxf(m, __shfl_xor_sync(0xffffffffu, m, 2));
                m = fmaxf(m, __shfl_xor_sync(0xffffffffu, m, 4));
                float e = expf(acc - m);   // inactive lanes: exp(-huge)=0
                float s = e;
                s += __shfl_xor_sync(0xffffffffu, s, 1);
                s += __shfl_xor_sync(0xffffffffu, s, 2);
                s += __shfl_xor_sync(0xffffffffu, s, 4);
                if (g < NGS) sm.gate_s[r][g] = e / s;
            }
        }
        __syncthreads();   // gate smem + wts reads settled before next iteration
    }

    // ================= PHASE 2: experts =================
    // Order (shared, task0, task1): shared input tile is the one already resident
    // after the gate pre-pass at levels where inputs differ.
    #pragma unroll 1
    for (int gi = 0; gi < 3; ++gi) {
        const int grp = (gi == 0) ? 2 : (gi - 1);   // 2, 0, 1
        const float* xin = (grp == 0) ? in0 : (grp == 1) ? in1 : insh;
        load_tile(xin);

        #pragma unroll 1
        for (int e = 0; e < 2; ++e) {
            const float* W;
            const float* bias;
            if (grp < 2) {
                int idx = grp * EP + e;
                W = we_task + (size_t)idx * D_DIM * U_DIM;
                bias = be_task + idx * U_DIM;
            } else {
                W = we_share + (size_t)e * D_DIM * U_DIM;
                bias = be_share + e * U_DIM;
            }

            u64 acc[4][2];
            #pragma unroll
            for (int r = 0; r < 4; ++r) { acc[r][0] = 0ull; acc[r][1] = 0ull; }

            #pragma unroll 1
            for (int kc = 0; kc < D_DIM; kc += KC) {
                __syncthreads();   // previous chunk readers done
                {
                    const int r = tid >> 4, c4 = tid & 15;
                    #pragma unroll
                    for (int rr = 0; rr < KC; rr += 16) {
                        float4 v = *reinterpret_cast<const float4*>(
                            W + (size_t)(kc + rr + r) * U_DIM + u0 + 4 * c4);
                        *reinterpret_cast<float4*>(&sm.wts[rr + r][4 * c4]) = v;
                    }
                }
                __syncthreads();
                #pragma unroll 16
                for (int kk = 0; kk < KC; ++kk) {
                    ulonglong2 xa = *reinterpret_cast<const ulonglong2*>(&sm.xdup[kc + kk][4 * ty]);
                    ulonglong2 xb = *reinterpret_cast<const ulonglong2*>(&sm.xdup[kc + kk][4 * ty + 2]);
                    ulonglong2 wv = *reinterpret_cast<const ulonglong2*>(&sm.wts[kk][4 * tx]);
                    ffma2(acc[0][0], xa.x, wv.x); ffma2(acc[0][1], xa.x, wv.y);
                    ffma2(acc[1][0], xa.y, wv.x); ffma2(acc[1][1], xa.y, wv.y);
                    ffma2(acc[2][0], xb.x, wv.x); ffma2(acc[2][1], xb.x, wv.y);
                    ffma2(acc[3][0], xb.y, wv.x); ffma2(acc[3][1], xb.y, wv.y);
                }
            }

            // ---- epilogue: bias + relu + gated accumulation ----
            float bv[4];
            #pragma unroll
            for (int c = 0; c < 4; ++c) bv[c] = bias[u0 + 4 * tx + c];
            #pragma unroll
            for (int r = 0; r < 4; ++r) {
                const int row = 4 * ty + r;
                float vals[4] = { lo32(acc[r][0]), hi32(acc[r][0]),
                                  lo32(acc[r][1]), hi32(acc[r][1]) };
                if (grp < 2) {
                    float gt = sm.gate_t[grp][row][e];
                    float gs = (!last) ? sm.gate_s[row][grp * EP + e] : 0.f;
                    #pragma unroll
                    for (int c = 0; c < 4; ++c) {
                        float v = fmaxf(vals[c] + bv[c], 0.f);
                        if (grp == 0) outA[r][c] = fmaf(gt, v, outA[r][c]);
                        else          outB[r][c] = fmaf(gt, v, outB[r][c]);
                        outC[r][c] = fmaf(gs, v, outC[r][c]);
                    }
                } else {
                    float g0 = sm.gate_t[0][row][EP + e];
                    float g1 = sm.gate_t[1][row][EP + e];
                    float gs = (!last) ? sm.gate_s[row][T_TASK * EP + e] : 0.f;
                    #pragma unroll
                    for (int c = 0; c < 4; ++c) {
                        float v = fmaxf(vals[c] + bv[c], 0.f);
                        outA[r][c] = fmaf(g0, v, outA[r][c]);
                        outB[r][c] = fmaf(g1, v, outB[r][c]);
                        outC[r][c] = fmaf(gs, v, outC[r][c]);
                    }
                }
            }
        }
    }

    // ---- store outputs ----
    #pragma unroll
    for (int r = 0; r < 4; ++r) {
        const size_t off = (size_t)(b0 + 4 * ty + r) * U_DIM + u0 + 4 * tx;
        *reinterpret_cast<float4*>(out0 + off) =
            make_float4(outA[r][0], outA[r][1], outA[r][2], outA[r][3]);
        *reinterpret_cast<float4*>(out1 + off) =
            make_float4(outB[r][0], outB[r][1], outB[r][2], outB[r][3]);
        if (!last)
            *reinterpret_cast<float4*>(outs + off) =
                make_float4(outC[r][0], outC[r][1], outC[r][2], outC[r][3]);
    }
}

extern "C" void kernel_launch(void* const* d_in, const int* in_sizes, int n_in,
                              void* d_out, int out_size) {
    const float* x        = (const float*)d_in[0];
    const float* we_task  = (const float*)d_in[1];  // [2][4][256][256]
    const float* be_task  = (const float*)d_in[2];  // [2][4][256]
    const float* we_share = (const float*)d_in[3];  // [2][2][256][256]
    const float* be_share = (const float*)d_in[4];  // [2][2][256]
    const float* wg_task  = (const float*)d_in[5];  // [2][2][256][4]
    const float* bg_task  = (const float*)d_in[6];  // [2][2][4]
    const float* wg_share = (const float*)d_in[7];  // [1][256][6]
    const float* bg_share = (const float*)d_in[8];  // [1][6]
    float* out = (float*)d_out;                     // [2][B][U]

    float* mid = nullptr;
    cudaGetSymbolAddress((void**)&mid, g_mid);
    float* m0 = mid;
    float* m1 = mid + (size_t)B_TOT * U_DIM;
    float* m2 = mid + 2 * (size_t)B_TOT * U_DIM;

    cudaFuncSetAttribute(ple_level_kernel,
                         cudaFuncAttributeMaxDynamicSharedMemorySize, (int)sizeof(Smem));

    dim3 grid(U_DIM / UU, B_TOT / BB);
    size_t shmem = sizeof(Smem);

    // Level 0: all three logical inputs are x; outputs -> scratch
    ple_level_kernel<<<grid, 256, shmem>>>(
        x, x, x,
        we_task, be_task, we_share, be_share,
        wg_task, bg_task, wg_share, bg_share,
        m0, m1, m2, /*last=*/0);

    // Level 1 (last): inputs from scratch; outputs -> d_out (task0, task1)
    ple_level_kernel<<<grid, 256, shmem>>>(
        m0, m1, m2,
        we_task + (size_t)T_TASK * EP * D_DIM * U_DIM, be_task + T_TASK * EP * U_DIM,
        we_share + (size_t)ES * D_DIM * U_DIM, be_share + ES * U_DIM,
        wg_task + T_TASK * D_DIM * NG, bg_task + T_TASK * NG,
        nullptr, nullptr,
        out, out + (size_t)B_TOT * U_DIM, nullptr, /*last=*/1);
}

// round 3
// speedup vs baseline: 1.0014x; 1.0014x over previous
#include <cuda_runtime.h>

typedef unsigned long long u64;

#define B_TOT 65536
#define D_DIM 256
#define U_DIM 256
#define T_TASK 2
#define EP 2
#define ES 2
#define NG 4      /* Ep+Es   */
#define NGS 6     /* T*Ep+Es */
#define BB 64
#define UU 64
#define KC 64

// Inter-level scratch: 3 x [B, U] fp32 (task0, task1, shared) = 192 MB static.
__device__ float g_mid[3ull * B_TOT * U_DIM];

struct Smem {
    u64   xdup[D_DIM][BB];          // input tile, transposed, each value duplicated as f32x2 (128 KB)
    float wts[KC][UU];              // weight k-chunk; also reused to stage gate weights (16 KB)
    float gate_t[T_TASK][BB][NG];   // per-task softmax gates
    float gate_s[BB][8];            // shared-path gates (6 used)
};

__device__ __forceinline__ u64 dupf(float v) {
    unsigned u = __float_as_uint(v);
    return ((u64)u << 32) | (u64)u;
}
__device__ __forceinline__ float lo32(u64 v) { return __uint_as_float((unsigned)(v & 0xffffffffull)); }
__device__ __forceinline__ float hi32(u64 v) { return __uint_as_float((unsigned)(v >> 32)); }
__device__ __forceinline__ void ffma2(u64& d, u64 a, u64 b) {
    asm("fma.rn.f32x2 %0, %1, %2, %0;" : "+l"(d) : "l"(a), "l"(b));
}

__global__ void __launch_bounds__(256, 1) ple_level_kernel(
    const float* __restrict__ in0, const float* __restrict__ in1, const float* __restrict__ insh,
    const float* __restrict__ we_task, const float* __restrict__ be_task,
    const float* __restrict__ we_share, const float* __restrict__ be_share,
    const float* __restrict__ wg_task, const float* __restrict__ bg_task,
    const float* __restrict__ wg_share, const float* __restrict__ bg_share,
    float* __restrict__ out0, float* __restrict__ out1, float* __restrict__ outs,
    int last)
{
    extern __shared__ char smem_raw[];
    Smem& sm = *reinterpret_cast<Smem*>(smem_raw);

    const int tid = threadIdx.x;
    const int tx = tid & 15;   // u direction (4 cols per thread)
    const int ty = tid >> 4;   // b direction (4 rows per thread)
    const int b0 = blockIdx.y * BB;
    const int u0 = blockIdx.x * UU;

    float outA[4][4], outB[4][4], outC[4][4];
    #pragma unroll
    for (int r = 0; r < 4; ++r)
        #pragma unroll
        for (int c = 0; c < 4; ++c) { outA[r][c] = 0.f; outB[r][c] = 0.f; outC[r][c] = 0.f; }

    const float* loaded = nullptr;

    // Load the [BB x D] input tile transposed + f32x2-duplicated into sm.xdup.
    auto load_tile = [&](const float* xin) {
        if (xin == loaded) return;
        __syncthreads();   // prior readers of xdup done
        const int row = tid & 63;
        const int cbase = (tid >> 6) * 16;
        const float4* src = reinterpret_cast<const float4*>(xin + (size_t)(b0 + row) * D_DIM);
        #pragma unroll 4
        for (int it = 0; it < 16; ++it) {
            int c4 = cbase + it;
            float4 v = src[c4];
            // lanes have consecutive rows -> contiguous 256B smem stores, conflict-free
            sm.xdup[4 * c4 + 0][row] = dupf(v.x);
            sm.xdup[4 * c4 + 1][row] = dupf(v.y);
            sm.xdup[4 * c4 + 2][row] = dupf(v.z);
            sm.xdup[4 * c4 + 3][row] = dupf(v.w);
        }
        loaded = xin;
        __syncthreads();   // xdup visible
    };

    // ================= PHASE 1: all gates (before any expert epilogue) =================
    const int n_gate_grps = last ? 2 : 3;
    #pragma unroll 1
    for (int gg = 0; gg < n_gate_grps; ++gg) {
        const float* xin = (gg == 0) ? in0 : (gg == 1) ? in1 : insh;
        load_tile(xin);

        __syncthreads();   // previous wts readers done
        float* wg_s = &sm.wts[0][0];
        if (gg < 2) {
            for (int i = tid; i < D_DIM * NG; i += 256) wg_s[i] = wg_task[gg * D_DIM * NG + i];
        } else {
            for (int i = tid; i < D_DIM * NGS; i += 256) wg_s[i] = wg_share[i];
        }
        __syncthreads();

        if (gg < 2) {
            const int r = tid >> 2, g = tid & 3;
            float acc = bg_task[gg * NG + g];
            #pragma unroll 8
            for (int d = 0; d < D_DIM; ++d)
                acc = fmaf(((const float*)&sm.xdup[d][r])[0], wg_s[d * NG + g], acc);
            float m = acc;
            m = fmaxf(m, __shfl_xor_sync(0xffffffffu, m, 1));
            m = fmaxf(m, __shfl_xor_sync(0xffffffffu, m, 2));
            float e = expf(acc - m);
            float s = e;
            s += __shfl_xor_sync(0xffffffffu, s, 1);
            s += __shfl_xor_sync(0xffffffffu, s, 2);
            sm.gate_t[gg][r][g] = e / s;
        } else {
            const int r0 = tid >> 3, g = tid & 7;
            #pragma unroll 1
            for (int h = 0; h < 2; ++h) {
                int r = r0 + 32 * h;
                float acc = -1e30f;
                if (g < NGS) {
                    acc = bg_share[g];
                    #pragma unroll 8
                    for (int d = 0; d < D_DIM; ++d)
                        acc = fmaf(((const float*)&sm.xdup[d][r])[0], wg_s[d * NGS + g], acc);
                }
                float m = acc;
                m = fmaxf(m, __shfl_xor_sync(0xffffffffu, m, 1));
                m = fmaxf(m, __shfl_xor_sync(0xffffffffu, m, 2));
                m = fmaxf(m, __shfl_xor_sync(0xffffffffu, m, 4));
                float e = expf(acc - m);   // inactive lanes: exp(-huge)=0
                float s = e;
                s += __shfl_xor_sync(0xffffffffu, s, 1);
                s += __shfl_xor_sync(0xffffffffu, s, 2);
                s += __shfl_xor_sync(0xffffffffu, s, 4);
                if (g < NGS) sm.gate_s[r][g] = e / s;
            }
        }
        __syncthreads();   // gate smem + wts reads settled before next iteration
    }

    // ================= PHASE 2: experts =================
    // Order (shared, task0, task1): shared input tile is the one already resident
    // after the gate pre-pass at levels where inputs differ.
    #pragma unroll 1
    for (int gi = 0; gi < 3; ++gi) {
        const int grp = (gi == 0) ? 2 : (gi - 1);   // 2, 0, 1
        const float* xin = (grp == 0) ? in0 : (grp == 1) ? in1 : insh;
        load_tile(xin);

        #pragma unroll 1
        for (int e = 0; e < 2; ++e) {
            const float* W;
            const float* bias;
            if (grp < 2) {
                int idx = grp * EP + e;
                W = we_task + (size_t)idx * D_DIM * U_DIM;
                bias = be_task + idx * U_DIM;
            } else {
                W = we_share + (size_t)e * D_DIM * U_DIM;
                bias = be_share + e * U_DIM;
            }

            u64 acc[4][2];
            #pragma unroll
            for (int r = 0; r < 4; ++r) { acc[r][0] = 0ull; acc[r][1] = 0ull; }

            #pragma unroll 1
            for (int kc = 0; kc < D_DIM; kc += KC) {
                __syncthreads();   // previous chunk readers done
                {
                    const int r = tid >> 4, c4 = tid & 15;
                    #pragma unroll
                    for (int rr = 0; rr < KC; rr += 16) {
                        float4 v = *reinterpret_cast<const float4*>(
                            W + (size_t)(kc + rr + r) * U_DIM + u0 + 4 * c4);
                        *reinterpret_cast<float4*>(&sm.wts[rr + r][4 * c4]) = v;
                    }
                }
                __syncthreads();
                #pragma unroll 16
                for (int kk = 0; kk < KC; ++kk) {
                    ulonglong2 xa = *reinterpret_cast<const ulonglong2*>(&sm.xdup[kc + kk][4 * ty]);
                    ulonglong2 xb = *reinterpret_cast<const ulonglong2*>(&sm.xdup[kc + kk][4 * ty + 2]);
                    ulonglong2 wv = *reinterpret_cast<const ulonglong2*>(&sm.wts[kk][4 * tx]);
                    ffma2(acc[0][0], xa.x, wv.x); ffma2(acc[0][1], xa.x, wv.y);
                    ffma2(acc[1][0], xa.y, wv.x); ffma2(acc[1][1], xa.y, wv.y);
                    ffma2(acc[2][0], xb.x, wv.x); ffma2(acc[2][1], xb.x, wv.y);
                    ffma2(acc[3][0], xb.y, wv.x); ffma2(acc[3][1], xb.y, wv.y);
                }
            }

            // ---- epilogue: bias + relu + gated accumulation ----
            float bv[4];
            #pragma unroll
            for (int c = 0; c < 4; ++c) bv[c] = bias[u0 + 4 * tx + c];
            #pragma unroll
            for (int r = 0; r < 4; ++r) {
                const int row = 4 * ty + r;
                float vals[4] = { lo32(acc[r][0]), hi32(acc[r][0]),
                                  lo32(acc[r][1]), hi32(acc[r][1]) };
                if (grp < 2) {
                    float gt = sm.gate_t[grp][row][e];
                    float gs = (!last) ? sm.gate_s[row][grp * EP + e] : 0.f;
                    #pragma unroll
                    for (int c = 0; c < 4; ++c) {
                        float v = fmaxf(vals[c] + bv[c], 0.f);
                        if (grp == 0) outA[r][c] = fmaf(gt, v, outA[r][c]);
                        else          outB[r][c] = fmaf(gt, v, outB[r][c]);
                        outC[r][c] = fmaf(gs, v, outC[r][c]);
                    }
                } else {
                    float g0 = sm.gate_t[0][row][EP + e];
                    float g1 = sm.gate_t[1][row][EP + e];
                    float gs = (!last) ? sm.gate_s[row][T_TASK * EP + e] : 0.f;
                    #pragma unroll
                    for (int c = 0; c < 4; ++c) {
                        float v = fmaxf(vals[c] + bv[c], 0.f);
                        outA[r][c] = fmaf(g0, v, outA[r][c]);
                        outB[r][c] = fmaf(g1, v, outB[r][c]);
                        outC[r][c] = fmaf(gs, v, outC[r][c]);
                    }
                }
            }
        }
    }

    // ---- store outputs ----
    #pragma unroll
    for (int r = 0; r < 4; ++r) {
        const size_t off = (size_t)(b0 + 4 * ty + r) * U_DIM + u0 + 4 * tx;
        *reinterpret_cast<float4*>(out0 + off) =
            make_float4(outA[r][0], outA[r][1], outA[r][2], outA[r][3]);
        *reinterpret_cast<float4*>(out1 + off) =
            make_float4(outB[r][0], outB[r][1], outB[r][2], outB[r][3]);
        if (!last)
            *reinterpret_cast<float4*>(outs + off) =
                make_float4(outC[r][0], outC[r][1], outC[r][2], outC[r][3]);
    }
}

extern "C" void kernel_launch(void* const* d_in, const int* in_sizes, int n_in,
                              void* d_out, int out_size) {
    const float* x        = (const float*)d_in[0];
    const float* we_task  = (const float*)d_in[1];  // [2][4][256][256]
    const float* be_task  = (const float*)d_in[2];  // [2][4][256]
    const float* we_share = (const float*)d_in[3];  // [2][2][256][256]
    const float* be_share = (const float*)d_in[4];  // [2][2][256]
    const float* wg_task  = (const float*)d_in[5];  // [2][2][256][4]
    const float* bg_task  = (const float*)d_in[6];  // [2][2][4]
    const float* wg_share = (const float*)d_in[7];  // [1][256][6]
    const float* bg_share = (const float*)d_in[8];  // [1][6]
    float* out = (float*)d_out;                     // [2][B][U]

    float* mid = nullptr;
    cudaGetSymbolAddress((void**)&mid, g_mid);
    float* m0 = mid;
    float* m1 = mid + (size_t)B_TOT * U_DIM;
    float* m2 = mid + 2 * (size_t)B_TOT * U_DIM;

    cudaFuncSetAttribute(ple_level_kernel,
                         cudaFuncAttributeMaxDynamicSharedMemorySize, (int)sizeof(Smem));

    dim3 grid(U_DIM / UU, B_TOT / BB);
    size_t shmem = sizeof(Smem);

    // Level 0: all three logical inputs are x; outputs -> scratch
    ple_level_kernel<<<grid, 256, shmem>>>(
        x, x, x,
        we_task, be_task, we_share, be_share,
        wg_task, bg_task, wg_share, bg_share,
        m0, m1, m2, /*last=*/0);

    // Level 1 (last): inputs from scratch; outputs -> d_out (task0, task1)
    ple_level_kernel<<<grid, 256, shmem>>>(
        m0, m1, m2,
        we_task + (size_t)T_TASK * EP * D_DIM * U_DIM, be_task + T_TASK * EP * U_DIM,
        we_share + (size_t)ES * D_DIM * U_DIM, be_share + ES * U_DIM,
        wg_task + T_TASK * D_DIM * NG, bg_task + T_TASK * NG,
        nullptr, nullptr,
        out, out + (size_t)B_TOT * U_DIM, nullptr, /*last=*/1);
}

// round 4
// speedup vs baseline: 1.0019x; 1.0006x over previous
#include <cuda_runtime.h>

typedef unsigned long long u64;

#define B_TOT 65536
#define D_DIM 256
#define U_DIM 256
#define T_TASK 2
#define EP 2
#define ES 2
#define NG 4      /* Ep+Es   */
#define NGS 6     /* T*Ep+Es */
#define BB 64
#define UU 64
#define KC 64

// Inter-level scratch: 3 x [B, U] fp32 (task0, task1, shared) = 192 MB static.
__device__ float g_mid[3ull * B_TOT * U_DIM];

struct Smem {
    u64   xdup[D_DIM][BB];          // input tile, transposed, each value duplicated as f32x2 (128 KB)
    float wts[KC][UU];              // weight k-chunk; also reused to stage gate weights (16 KB)
    float gate_t[T_TASK][BB][NG];   // per-task softmax gates
    float gate_s[BB][8];            // shared-path gates (6 used)
};

__device__ __forceinline__ u64 dupf(float v) {
    unsigned u = __float_as_uint(v);
    return ((u64)u << 32) | (u64)u;
}
__device__ __forceinline__ float lo32(u64 v) { return __uint_as_float((unsigned)(v & 0xffffffffull)); }
__device__ __forceinline__ float hi32(u64 v) { return __uint_as_float((unsigned)(v >> 32)); }
__device__ __forceinline__ void ffma2(u64& d, u64 a, u64 b) {
    asm("fma.rn.f32x2 %0, %1, %2, %0;" : "+l"(d) : "l"(a), "l"(b));
}

__global__ void __launch_bounds__(256, 1) ple_level_kernel(
    const float* __restrict__ in0, const float* __restrict__ in1, const float* __restrict__ insh,
    const float* __restrict__ we_task, const float* __restrict__ be_task,
    const float* __restrict__ we_share, const float* __restrict__ be_share,
    const float* __restrict__ wg_task, const float* __restrict__ bg_task,
    const float* __restrict__ wg_share, const float* __restrict__ bg_share,
    float* __restrict__ out0, float* __restrict__ out1, float* __restrict__ outs,
    int last)
{
    extern __shared__ char smem_raw[];
    Smem& sm = *reinterpret_cast<Smem*>(smem_raw);

    const int tid = threadIdx.x;
    const int tx = tid & 15;   // u direction (4 cols per thread)
    const int ty = tid >> 4;   // b direction (4 rows per thread)
    const int b0 = blockIdx.y * BB;
    const int u0 = blockIdx.x * UU;

    float outA[4][4], outB[4][4], outC[4][4];
    #pragma unroll
    for (int r = 0; r < 4; ++r)
        #pragma unroll
        for (int c = 0; c < 4; ++c) { outA[r][c] = 0.f; outB[r][c] = 0.f; outC[r][c] = 0.f; }

    const float* loaded = nullptr;

    // Load the [BB x D] input tile transposed + f32x2-duplicated into sm.xdup.
    auto load_tile = [&](const float* xin) {
        if (xin == loaded) return;
        __syncthreads();   // prior readers of xdup done
        const int row = tid & 63;
        const int cbase = (tid >> 6) * 16;
        const float4* src = reinterpret_cast<const float4*>(xin + (size_t)(b0 + row) * D_DIM);
        #pragma unroll 4
        for (int it = 0; it < 16; ++it) {
            int c4 = cbase + it;
            float4 v = src[c4];
            // lanes have consecutive rows -> contiguous 256B smem stores, conflict-free
            sm.xdup[4 * c4 + 0][row] = dupf(v.x);
            sm.xdup[4 * c4 + 1][row] = dupf(v.y);
            sm.xdup[4 * c4 + 2][row] = dupf(v.z);
            sm.xdup[4 * c4 + 3][row] = dupf(v.w);
        }
        loaded = xin;
        __syncthreads();   // xdup visible
    };

    // ================= PHASE 1: all gates (before any expert epilogue) =================
    const int n_gate_grps = last ? 2 : 3;
    #pragma unroll 1
    for (int gg = 0; gg < n_gate_grps; ++gg) {
        const float* xin = (gg == 0) ? in0 : (gg == 1) ? in1 : insh;
        load_tile(xin);

        __syncthreads();   // previous wts readers done
        float* wg_s = &sm.wts[0][0];
        if (gg < 2) {
            for (int i = tid; i < D_DIM * NG; i += 256) wg_s[i] = wg_task[gg * D_DIM * NG + i];
        } else {
            for (int i = tid; i < D_DIM * NGS; i += 256) wg_s[i] = wg_share[i];
        }
        __syncthreads();

        if (gg < 2) {
            const int r = tid >> 2, g = tid & 3;
            float acc = bg_task[gg * NG + g];
            #pragma unroll 8
            for (int d = 0; d < D_DIM; ++d)
                acc = fmaf(((const float*)&sm.xdup[d][r])[0], wg_s[d * NG + g], acc);
            float m = acc;
            m = fmaxf(m, __shfl_xor_sync(0xffffffffu, m, 1));
            m = fmaxf(m, __shfl_xor_sync(0xffffffffu, m, 2));
            float e = expf(acc - m);
            float s = e;
            s += __shfl_xor_sync(0xffffffffu, s, 1);
            s += __shfl_xor_sync(0xffffffffu, s, 2);
            sm.gate_t[gg][r][g] = e / s;
        } else {
            const int r0 = tid >> 3, g = tid & 7;
            #pragma unroll 1
            for (int h = 0; h < 2; ++h) {
                int r = r0 + 32 * h;
                float acc = -1e30f;
                if (g < NGS) {
                    acc = bg_share[g];
                    #pragma unroll 8
                    for (int d = 0; d < D_DIM; ++d)
                        acc = fmaf(((const float*)&sm.xdup[d][r])[0], wg_s[d * NGS + g], acc);
                }
                float m = acc;
                m = fmaxf(m, __shfl_xor_sync(0xffffffffu, m, 1));
                m = fmaxf(m, __shfl_xor_sync(0xffffffffu, m, 2));
                m = fmaxf(m, __shfl_xor_sync(0xffffffffu, m, 4));
                float e = expf(acc - m);   // inactive lanes: exp(-huge)=0
                float s = e;
                s += __shfl_xor_sync(0xffffffffu, s, 1);
                s += __shfl_xor_sync(0xffffffffu, s, 2);
                s += __shfl_xor_sync(0xffffffffu, s, 4);
                if (g < NGS) sm.gate_s[r][g] = e / s;
            }
        }
        __syncthreads();   // gate smem + wts reads settled before next iteration
    }

    // ================= PHASE 2: experts =================
    // Order (shared, task0, task1): shared input tile is the one already resident
    // after the gate pre-pass at levels where inputs differ.
    #pragma unroll 1
    for (int gi = 0; gi < 3; ++gi) {
        const int grp = (gi == 0) ? 2 : (gi - 1);   // 2, 0, 1
        const float* xin = (grp == 0) ? in0 : (grp == 1) ? in1 : insh;
        load_tile(xin);

        #pragma unroll 1
        for (int e = 0; e < 2; ++e) {
            const float* W;
            const float* bias;
            if (grp < 2) {
                int idx = grp * EP + e;
                W = we_task + (size_t)idx * D_DIM * U_DIM;
                bias = be_task + idx * U_DIM;
            } else {
                W = we_share + (size_t)e * D_DIM * U_DIM;
                bias = be_share + e * U_DIM;
            }

            u64 acc[4][2];
            #pragma unroll
            for (int r = 0; r < 4; ++r) { acc[r][0] = 0ull; acc[r][1] = 0ull; }

            #pragma unroll 1
            for (int kc = 0; kc < D_DIM; kc += KC) {
                __syncthreads();   // previous chunk readers done
                {
                    const int r = tid >> 4, c4 = tid & 15;
                    #pragma unroll
                    for (int rr = 0; rr < KC; rr += 16) {
                        float4 v = *reinterpret_cast<const float4*>(
                            W + (size_t)(kc + rr + r) * U_DIM + u0 + 4 * c4);
                        *reinterpret_cast<float4*>(&sm.wts[rr + r][4 * c4]) = v;
                    }
                }
                __syncthreads();
                #pragma unroll 16
                for (int kk = 0; kk < KC; ++kk) {
                    ulonglong2 xa = *reinterpret_cast<const ulonglong2*>(&sm.xdup[kc + kk][4 * ty]);
                    ulonglong2 xb = *reinterpret_cast<const ulonglong2*>(&sm.xdup[kc + kk][4 * ty + 2]);
                    ulonglong2 wv = *reinterpret_cast<const ulonglong2*>(&sm.wts[kk][4 * tx]);
                    ffma2(acc[0][0], xa.x, wv.x); ffma2(acc[0][1], xa.x, wv.y);
                    ffma2(acc[1][0], xa.y, wv.x); ffma2(acc[1][1], xa.y, wv.y);
                    ffma2(acc[2][0], xb.x, wv.x); ffma2(acc[2][1], xb.x, wv.y);
                    ffma2(acc[3][0], xb.y, wv.x); ffma2(acc[3][1], xb.y, wv.y);
                }
            }

            // ---- epilogue: bias + relu + gated accumulation ----
            float bv[4];
            #pragma unroll
            for (int c = 0; c < 4; ++c) bv[c] = bias[u0 + 4 * tx + c];
            #pragma unroll
            for (int r = 0; r < 4; ++r) {
                const int row = 4 * ty + r;
                float vals[4] = { lo32(acc[r][0]), hi32(acc[r][0]),
                                  lo32(acc[r][1]), hi32(acc[r][1]) };
                if (grp < 2) {
                    float gt = sm.gate_t[grp][row][e];
                    float gs = (!last) ? sm.gate_s[row][grp * EP + e] : 0.f;
                    #pragma unroll
                    for (int c = 0; c < 4; ++c) {
                        float v = fmaxf(vals[c] + bv[c], 0.f);
                        if (grp == 0) outA[r][c] = fmaf(gt, v, outA[r][c]);
                        else          outB[r][c] = fmaf(gt, v, outB[r][c]);
                        outC[r][c] = fmaf(gs, v, outC[r][c]);
                    }
                } else {
                    float g0 = sm.gate_t[0][row][EP + e];
                    float g1 = sm.gate_t[1][row][EP + e];
                    float gs = (!last) ? sm.gate_s[row][T_TASK * EP + e] : 0.f;
                    #pragma unroll
                    for (int c = 0; c < 4; ++c) {
                        float v = fmaxf(vals[c] + bv[c], 0.f);
                        outA[r][c] = fmaf(g0, v, outA[r][c]);
                        outB[r][c] = fmaf(g1, v, outB[r][c]);
                        outC[r][c] = fmaf(gs, v, outC[r][c]);
                    }
                }
            }
        }
    }

    // ---- store outputs ----
    #pragma unroll
    for (int r = 0; r < 4; ++r) {
        const size_t off = (size_t)(b0 + 4 * ty + r) * U_DIM + u0 + 4 * tx;
        *reinterpret_cast<float4*>(out0 + off) =
            make_float4(outA[r][0], outA[r][1], outA[r][2], outA[r][3]);
        *reinterpret_cast<float4*>(out1 + off) =
            make_float4(outB[r][0], outB[r][1], outB[r][2], outB[r][3]);
        if (!last)
            *reinterpret_cast<float4*>(outs + off) =
                make_float4(outC[r][0], outC[r][1], outC[r][2], outC[r][3]);
    }
}

extern "C" void kernel_launch(void* const* d_in, const int* in_sizes, int n_in,
                              void* d_out, int out_size) {
    const float* x        = (const float*)d_in[0];
    const float* we_task  = (const float*)d_in[1];  // [2][4][256][256]
    const float* be_task  = (const float*)d_in[2];  // [2][4][256]
    const float* we_share = (const float*)d_in[3];  // [2][2][256][256]
    const float* be_share = (const float*)d_in[4];  // [2][2][256]
    const float* wg_task  = (const float*)d_in[5];  // [2][2][256][4]
    const float* bg_task  = (const float*)d_in[6];  // [2][2][4]
    const float* wg_share = (const float*)d_in[7];  // [1][256][6]
    const float* bg_share = (const float*)d_in[8];  // [1][6]
    float* out = (float*)d_out;                     // [2][B][U]

    float* mid = nullptr;
    cudaGetSymbolAddress((void**)&mid, g_mid);
    float* m0 = mid;
    float* m1 = mid + (size_t)B_TOT * U_DIM;
    float* m2 = mid + 2 * (size_t)B_TOT * U_DIM;

    cudaFuncSetAttribute(ple_level_kernel,
                         cudaFuncAttributeMaxDynamicSharedMemorySize, (int)sizeof(Smem));

    dim3 grid(U_DIM / UU, B_TOT / BB);
    size_t shmem = sizeof(Smem);

    // Level 0: all three logical inputs are x; outputs -> scratch
    ple_level_kernel<<<grid, 256, shmem>>>(
        x, x, x,
        we_task, be_task, we_share, be_share,
        wg_task, bg_task, wg_share, bg_share,
        m0, m1, m2, /*last=*/0);

    // Level 1 (last): inputs from scratch; outputs -> d_out (task0, task1)
    ple_level_kernel<<<grid, 256, shmem>>>(
        m0, m1, m2,
        we_task + (size_t)T_TASK * EP * D_DIM * U_DIM, be_task + T_TASK * EP * U_DIM,
        we_share + (size_t)ES * D_DIM * U_DIM, be_share + ES * U_DIM,
        wg_task + T_TASK * D_DIM * NG, bg_task + T_TASK * NG,
        nullptr, nullptr,
        out, out + (size_t)B_TOT * U_DIM, nullptr, /*last=*/1);
}